// round 3
// baseline (speedup 1.0000x reference)
#include <cuda_runtime.h>

// SSIM loss, fully fused, f32x2-packed:
// 5 depthwise separable 11x11 Gaussian convs (p, t, p², t², p·t) + SSIM map
// + mean in one pass. Inputs staged in smem as packed (p,t) float2 so one
// LDS.64 + fma.rn.f32x2 handles two fields at once; h-pass intermediates
// stored as (h1,h2) / (hpp,htt) pairs. Per-block partial sums go to unique
// slots (no same-address atomic serialization); final kernel reduces.

#define TW    32
#define TH    32
#define HALO  5
#define EW    (TW + 2*HALO)   // 42
#define EH    (TH + 2*HALO)   // 42
#define SP2   43              // pitch (in float2) for packed input tile
#define HP2   33              // pitch (in float2 / float) for h-pass arrays

#define IMG_H 512
#define IMG_W 512
#define N_PLANES 96
#define NBLK  (16*16*96)      // 24576
#define N_PIX 25165824.0

typedef unsigned long long ull;

__device__ constexpr float GW[11] = {
    0.00102838f, 0.00759877f, 0.03600077f, 0.10936071f, 0.21300553f,
    0.26601175f,
    0.21300553f, 0.10936071f, 0.03600077f, 0.00759877f, 0.00102838f
};

__device__ float g_part[NBLK];

__device__ __forceinline__ ull pk2(float lo, float hi) {
    ull r;
    asm("mov.b64 %0, {%1, %2};" : "=l"(r) : "f"(lo), "f"(hi));
    return r;
}
__device__ __forceinline__ void upk2(float& lo, float& hi, ull v) {
    asm("mov.b64 {%0, %1}, %2;" : "=f"(lo), "=f"(hi) : "l"(v));
}
__device__ __forceinline__ void fma2(ull& d, ull a, ull b) {
    asm("fma.rn.f32x2 %0, %1, %2, %0;" : "+l"(d) : "l"(a), "l"(b));
}
__device__ __forceinline__ ull mul2(ull a, ull b) {
    ull d;
    asm("mul.rn.f32x2 %0, %1, %2;" : "=l"(d) : "l"(a), "l"(b));
    return d;
}

__global__ __launch_bounds__(512)
void ssim_tile_kernel(const float* __restrict__ pred,
                      const float* __restrict__ targ)
{
    __shared__ ull   spt[EH][SP2];    // packed (p, t)
    __shared__ ull   hA [EH][HP2];    // packed (conv_h p, conv_h t)
    __shared__ ull   hB [EH][HP2];    // packed (conv_h p², conv_h t²)
    __shared__ float hC [EH][HP2];    // conv_h (p·t)
    __shared__ float red[16];

    const int tid = threadIdx.x;
    const int ty0 = blockIdx.y * TH;
    const int tx0 = blockIdx.x * TW;
    const size_t pbase = (size_t)blockIdx.z * (IMG_H * IMG_W);

    // ---- load halo tiles, packed (zero padding at borders) ----
    for (int idx = tid; idx < EH * EW; idx += 512) {
        int r = idx / EW;
        int c = idx - r * EW;
        int gy = ty0 + r - HALO;
        int gx = tx0 + c - HALO;
        bool ok = ((unsigned)gy < (unsigned)IMG_H) & ((unsigned)gx < (unsigned)IMG_W);
        float a = 0.f, b = 0.f;
        if (ok) {
            size_t off = pbase + (size_t)gy * IMG_W + gx;
            a = pred[off];
            b = targ[off];
        }
        spt[r][c] = pk2(a, b);
    }
    __syncthreads();

    // ---- horizontal pass: 42 rows x 8 col-groups = 336 items, 4 cols each ----
    if (tid < EH * (TW / 4)) {
        int r  = tid >> 3;
        int c0 = (tid & 7) * 4;
        ull  a01[4], a23[4];
        float a4[4];
        #pragma unroll
        for (int j = 0; j < 4; j++) { a01[j] = 0; a23[j] = 0; a4[j] = 0.f; }

        #pragma unroll
        for (int i = 0; i < 14; i++) {
            ull pab = spt[r][c0 + i];
            ull p2  = mul2(pab, pab);          // (p², t²)
            float a, b;
            upk2(a, b, pab);
            float ab = a * b;
            #pragma unroll
            for (int j = 0; j < 4; j++) {
                int k = i - j;
                if (k >= 0 && k <= 10) {
                    ull w2 = pk2(GW[k], GW[k]);
                    fma2(a01[j], pab, w2);
                    fma2(a23[j], p2,  w2);
                    a4[j] = fmaf(GW[k], ab, a4[j]);
                }
            }
        }
        #pragma unroll
        for (int j = 0; j < 4; j++) {
            hA[r][c0 + j] = a01[j];
            hB[r][c0 + j] = a23[j];
            hC[r][c0 + j] = a4[j];
        }
    }
    __syncthreads();

    // ---- vertical pass + SSIM: thread -> (x, 2 adjacent y) ----
    const int x  = tid & 31;
    const int y0 = (tid >> 5) * 2;

    ull  vA[2] = {0, 0}, vB[2] = {0, 0};
    float v4[2] = {0.f, 0.f};

    #pragma unroll
    for (int i = 0; i < 12; i++) {
        int row = y0 + i;
        ull  cab = hA[row][x];
        ull  cpt = hB[row][x];
        float cc = hC[row][x];
        #pragma unroll
        for (int j = 0; j < 2; j++) {
            int k = i - j;
            if (k >= 0 && k <= 10) {
                ull w2 = pk2(GW[k], GW[k]);
                fma2(vA[j], cab, w2);
                fma2(vB[j], cpt, w2);
                v4[j] = fmaf(GW[k], cc, v4[j]);
            }
        }
    }

    float lsum = 0.f;
    const float C1 = 1e-4f;
    const float C2 = 9e-4f;
    #pragma unroll
    for (int j = 0; j < 2; j++) {
        float mu1, mu2, epp, ett;
        upk2(mu1, mu2, vA[j]);
        upk2(epp, ett, vB[j]);
        float m1s = mu1 * mu1;
        float m2s = mu2 * mu2;
        float m12 = mu1 * mu2;
        float s1  = epp - m1s;
        float s2  = ett - m2s;
        float s12 = v4[j] - m12;
        float num = (2.f * m12 + C1) * (2.f * s12 + C2);
        float den = (m1s + m2s + C1) * (s1 + s2 + C2) + 1e-8f;
        lsum += __fdividef(num, den);
    }

    // ---- block reduce, write unique partial slot ----
    #pragma unroll
    for (int o = 16; o; o >>= 1)
        lsum += __shfl_xor_sync(0xffffffffu, lsum, o);
    if ((tid & 31) == 0) red[tid >> 5] = lsum;
    __syncthreads();
    if (tid == 0) {
        float s = 0.f;
        #pragma unroll
        for (int w = 0; w < 16; w++) s += red[w];
        int bid = (blockIdx.z * 16 + blockIdx.y) * 16 + blockIdx.x;
        g_part[bid] = s;
    }
}

__global__ __launch_bounds__(1024)
void ssim_fin_kernel(float* __restrict__ out)
{
    __shared__ double dred[32];
    const int tid = threadIdx.x;

    double s = 0.0;
    for (int i = tid; i < NBLK; i += 1024) s += (double)g_part[i];

    #pragma unroll
    for (int o = 16; o; o >>= 1)
        s += __shfl_xor_sync(0xffffffffu, s, o);
    if ((tid & 31) == 0) dred[tid >> 5] = s;
    __syncthreads();
    if (tid == 0) {
        double t = 0.0;
        #pragma unroll
        for (int w = 0; w < 32; w++) t += dred[w];
        out[0] = (float)(1.0 - t * (1.0 / N_PIX));
    }
}

extern "C" void kernel_launch(void* const* d_in, const int* in_sizes, int n_in,
                              void* d_out, int out_size)
{
    const float* pred = (const float*)d_in[0];
    const float* targ = (const float*)d_in[1];

    dim3 grid(IMG_W / TW, IMG_H / TH, N_PLANES);   // 16 x 16 x 96
    ssim_tile_kernel<<<grid, 512>>>(pred, targ);
    ssim_fin_kernel<<<1, 1024>>>((float*)d_out);
}

// round 4
// speedup vs baseline: 1.5401x; 1.5401x over previous
#include <cuda_runtime.h>

// SSIM loss, fused, U/V-transformed + f32x2-packed.
// u=p+t, v=p-t. Only 4 separable 11x11 convs needed: u, v, u^2, v^2,
// which pack into TWO f32x2 conv fields: X=(u,v), Y=(u2,v2).
//   A=conv(u)=mu1+mu2, B=conv(v)=mu1-mu2, C=conv(u2), D=conv(v2)
//   2*m12=(A^2-B^2)/2, m1s+m2s=(A^2+B^2)/2,
//   2*s12=(C-D)/2-2*m12, s1+s2=(C+D)/2-(m1s+m2s)
// 352 thr/block: h-pass 336 items (1/thread), v-pass 3 outputs/thread.
// Per-block partials to unique slots; vectorized final reduce.

#define TW    32
#define TH    32
#define HALO  5
#define EW    42
#define EH    42
#define XP    43              // pitch (ull) input tile
#define HP    33              // pitch (ull) h-pass arrays

#define IMG_H 512
#define IMG_W 512
#define N_PLANES 96
#define NBLK  (16*16*96)      // 24576
#define N_PIX 25165824.0

typedef unsigned long long ull;

__device__ constexpr float GW[11] = {
    0.00102838f, 0.00759877f, 0.03600077f, 0.10936071f, 0.21300553f,
    0.26601175f,
    0.21300553f, 0.10936071f, 0.03600077f, 0.00759877f, 0.00102838f
};

__device__ float4 g_part4[NBLK / 4];

__device__ __forceinline__ ull pk2(float lo, float hi) {
    ull r;
    asm("mov.b64 %0, {%1, %2};" : "=l"(r) : "f"(lo), "f"(hi));
    return r;
}
__device__ __forceinline__ void upk2(float& lo, float& hi, ull v) {
    asm("mov.b64 {%0, %1}, %2;" : "=f"(lo), "=f"(hi) : "l"(v));
}
__device__ __forceinline__ void fma2(ull& d, ull a, ull b) {
    asm("fma.rn.f32x2 %0, %1, %2, %0;" : "+l"(d) : "l"(a), "l"(b));
}
__device__ __forceinline__ ull mul2(ull a, ull b) {
    ull d;
    asm("mul.rn.f32x2 %0, %1, %2;" : "=l"(d) : "l"(a), "l"(b));
    return d;
}

__global__ __launch_bounds__(352)
void ssim_tile_kernel(const float* __restrict__ pred,
                      const float* __restrict__ targ)
{
    __shared__ ull sX[EH][XP];    // (u, v)
    __shared__ ull hX[EH][HP];    // (A, B)
    __shared__ ull hY[EH][HP];    // (C, D)
    __shared__ float red[11];

    const int tid = threadIdx.x;
    const int ty0 = blockIdx.y * TH;
    const int tx0 = blockIdx.x * TW;
    const size_t pbase = (size_t)blockIdx.z * (IMG_H * IMG_W);

    // ---- load halo tile, compute (u,v), store packed ----
    #pragma unroll
    for (int it = 0; it < 6; it++) {
        int idx = tid + it * 352;
        if (idx < EH * EW) {
            int r = idx / EW;
            int c = idx - r * EW;
            int gy = ty0 + r - HALO;
            int gx = tx0 + c - HALO;
            bool ok = ((unsigned)gy < (unsigned)IMG_H) & ((unsigned)gx < (unsigned)IMG_W);
            float a = 0.f, b = 0.f;
            if (ok) {
                size_t off = pbase + (size_t)gy * IMG_W + gx;
                a = pred[off];
                b = targ[off];
            }
            sX[r][c] = pk2(a + b, a - b);
        }
    }
    __syncthreads();

    // ---- horizontal pass: 336 items (42 rows x 8 groups), 4 outputs each ----
    if (tid < EH * (TW / 4)) {
        const int r  = tid >> 3;
        const int c0 = (tid & 7) * 4;
        ull aX[4] = {0, 0, 0, 0};
        ull aY[4] = {0, 0, 0, 0};

        #pragma unroll
        for (int i = 0; i < 14; i++) {
            ull X = sX[r][c0 + i];
            ull Y = mul2(X, X);
            #pragma unroll
            for (int j = 0; j < 4; j++) {
                int k = i - j;
                if (k >= 0 && k <= 10) {
                    ull w2 = pk2(GW[k], GW[k]);
                    fma2(aX[j], X, w2);
                    fma2(aY[j], Y, w2);
                }
            }
        }
        #pragma unroll
        for (int j = 0; j < 4; j++) {
            hX[r][c0 + j] = aX[j];
            hY[r][c0 + j] = aY[j];
        }
    }
    __syncthreads();

    // ---- vertical pass + SSIM: thread -> (x, 3 adjacent y) ----
    const int x  = tid & 31;
    const int yg = tid >> 5;          // 0..10
    const int y0 = yg * 3;            // yg=10 -> rows 30,31 (+1 discarded)

    ull vX[3] = {0, 0, 0};
    ull vY[3] = {0, 0, 0};

    #pragma unroll
    for (int i = 0; i < 13; i++) {
        int row = y0 + i;
        if (row > EH - 1) row = EH - 1;   // only hits discarded output
        ull cX = hX[row][x];
        ull cY = hY[row][x];
        #pragma unroll
        for (int j = 0; j < 3; j++) {
            int k = i - j;
            if (k >= 0 && k <= 10) {
                ull w2 = pk2(GW[k], GW[k]);
                fma2(vX[j], cX, w2);
                fma2(vY[j], cY, w2);
            }
        }
    }

    float lsum = 0.f;
    const float C1 = 1e-4f;
    const float C2 = 9e-4f;
    #pragma unroll
    for (int j = 0; j < 3; j++) {
        if (y0 + j < TH) {
            float A, B, Cv, Dv;
            upk2(A, B, vX[j]);
            upk2(Cv, Dv, vY[j]);
            float A2 = A * A;
            float B2 = B * B;
            float t2m12 = (A2 - B2) * 0.5f;          // 2*mu1*mu2
            float msum  = (A2 + B2) * 0.5f;          // mu1^2 + mu2^2
            float t2s12 = (Cv - Dv) * 0.5f - t2m12;  // 2*sigma12
            float ssum  = (Cv + Dv) * 0.5f - msum;   // sigma1^2 + sigma2^2
            float num = (t2m12 + C1) * (t2s12 + C2);
            float den = (msum + C1) * (ssum + C2) + 1e-8f;
            lsum += __fdividef(num, den);
        }
    }

    // ---- block reduce, unique partial slot ----
    #pragma unroll
    for (int o = 16; o; o >>= 1)
        lsum += __shfl_xor_sync(0xffffffffu, lsum, o);
    if ((tid & 31) == 0) red[tid >> 5] = lsum;
    __syncthreads();
    if (tid == 0) {
        float s = 0.f;
        #pragma unroll
        for (int w = 0; w < 11; w++) s += red[w];
        int bid = (blockIdx.z * 16 + blockIdx.y) * 16 + blockIdx.x;
        ((float*)g_part4)[bid] = s;
    }
}

__global__ __launch_bounds__(1024)
void ssim_fin_kernel(float* __restrict__ out)
{
    __shared__ double dred[32];
    const int tid = threadIdx.x;

    double s = 0.0;
    #pragma unroll
    for (int it = 0; it < 6; it++) {
        float4 v = g_part4[tid + it * 1024];
        s += (double)v.x + (double)v.y + (double)v.z + (double)v.w;
    }

    #pragma unroll
    for (int o = 16; o; o >>= 1)
        s += __shfl_xor_sync(0xffffffffu, s, o);
    if ((tid & 31) == 0) dred[tid >> 5] = s;
    __syncthreads();
    if (tid == 0) {
        double t = 0.0;
        #pragma unroll
        for (int w = 0; w < 32; w++) t += dred[w];
        out[0] = (float)(1.0 - t * (1.0 / N_PIX));
    }
}

extern "C" void kernel_launch(void* const* d_in, const int* in_sizes, int n_in,
                              void* d_out, int out_size)
{
    const float* pred = (const float*)d_in[0];
    const float* targ = (const float*)d_in[1];

    dim3 grid(IMG_W / TW, IMG_H / TH, N_PLANES);   // 16 x 16 x 96
    ssim_tile_kernel<<<grid, 352>>>(pred, targ);
    ssim_fin_kernel<<<1, 1024>>>((float*)d_out);
}